// round 3
// baseline (speedup 1.0000x reference)
#include <cuda_runtime.h>

// CenterLoss collapses algebraically: after masking, only the true-label
// column survives; the other C-1 zeros clamp to 1e-12 each.
//   loss = sum_n clamp(||x_n - c_{lab_n}||^2, 1e-12, 1e12) + N*(C-1)*1e-12
// So no N x C GEMM is needed — just a gathered per-row squared distance.
//
// Single fused kernel: one CTA per row; last CTA to finish (atomic counter)
// reduces all 4096 partials in fixed index order (bitwise deterministic),
// adds the clamp constant, writes the scalar, resets the counter for the
// next graph replay.

#define N_ROWS 4096      // 16 * 256
#define FEAT_DIM 512
#define NUM_CLASSES 10000

__device__ float g_row_partials[N_ROWS];
__device__ unsigned int g_done_count = 0;

__global__ __launch_bounds__(128) void center_loss_fused_kernel(
    const float* __restrict__ x,
    const int* __restrict__ labels,
    const float* __restrict__ centers,
    float* __restrict__ out)
{
    const int row = blockIdx.x;
    const int t = threadIdx.x;

    int c = labels[row];
    c = min(max(c, 0), NUM_CLASSES - 1);   // defensive: never OOB gather

    const float4* __restrict__ x4 =
        reinterpret_cast<const float4*>(x + (size_t)row * FEAT_DIM);
    const float4* __restrict__ c4 =
        reinterpret_cast<const float4*>(centers + (size_t)c * FEAT_DIM);

    float4 a = x4[t];
    float4 b = c4[t];
    float d0 = a.x - b.x;
    float d1 = a.y - b.y;
    float d2 = a.z - b.z;
    float d3 = a.w - b.w;
    float s = d0 * d0 + d1 * d1 + d2 * d2 + d3 * d3;

    // warp reduce
    #pragma unroll
    for (int o = 16; o > 0; o >>= 1)
        s += __shfl_xor_sync(0xffffffffu, s, o);

    __shared__ float ws[4];
    __shared__ bool is_last;
    if ((t & 31) == 0) ws[t >> 5] = s;
    __syncthreads();

    if (t == 0) {
        float tot = ws[0] + ws[1] + ws[2] + ws[3];
        // clamp (identity in practice: dist ~ 1000, but match reference)
        tot = fminf(fmaxf(tot, 1e-12f), 1e12f);
        g_row_partials[row] = tot;
        __threadfence();
        unsigned int v = atomicAdd(&g_done_count, 1u);
        is_last = (v == (unsigned int)(gridDim.x - 1));
    }
    __syncthreads();

    if (is_last) {
        // All partials are globally visible (threadfence + atomic acquire).
        // Fixed-order strided sum -> deterministic across runs.
        float acc = 0.0f;
        #pragma unroll
        for (int i = t; i < N_ROWS; i += 128)
            acc += g_row_partials[i];

        #pragma unroll
        for (int o = 16; o > 0; o >>= 1)
            acc += __shfl_xor_sync(0xffffffffu, acc, o);

        __shared__ float fs[4];
        if ((t & 31) == 0) fs[t >> 5] = acc;
        __syncthreads();

        if (t == 0) {
            const float zero_clamp_sum =
                (float)((double)N_ROWS * (double)(NUM_CLASSES - 1) * 1e-12);
            out[0] = (fs[0] + fs[1] + fs[2] + fs[3]) + zero_clamp_sum;
            g_done_count = 0;   // reset for next graph replay
        }
    }
}

extern "C" void kernel_launch(void* const* d_in, const int* in_sizes, int n_in,
                              void* d_out, int out_size)
{
    const float* x       = (const float*)d_in[0];  // (16,256,512) f32
    const int*   labels  = (const int*)d_in[1];    // (16,256) int32
    const float* centers = (const float*)d_in[2];  // (10000,512) f32
    float*       out     = (float*)d_out;          // scalar

    (void)in_sizes; (void)n_in; (void)out_size;

    center_loss_fused_kernel<<<N_ROWS, 128>>>(x, labels, centers, out);
}

// round 4
// speedup vs baseline: 1.2907x; 1.2907x over previous
#include <cuda_runtime.h>

// CenterLoss collapses algebraically: after masking, only the true-label
// column survives; the other C-1 zeros clamp to 1e-12 each.
//   loss = sum_n clamp(||x_n - c_{lab_n}||^2, 1e-12, 1e12) + N*(C-1)*1e-12
//
// Persistent layout: 128 CTAs x 256 threads. CTA b owns rows [b*32, b*32+32).
// Warp w (0..7) handles rows b*32 + w*4 + {0..3}, 4 float4 loads per lane
// per operand per row -> 8 outstanding loads (latency-hiding MLP), labels
// prefetched to smem. Last CTA (atomic counter over only 128 CTAs) does the
// fixed-order final reduction -> deterministic, ~zero tail cost.

#define N_ROWS 4096      // 16 * 256
#define FEAT_DIM 512
#define F4_PER_ROW (FEAT_DIM / 4)   // 128
#define NUM_CLASSES 10000
#define NUM_CTAS 128
#define ROWS_PER_CTA (N_ROWS / NUM_CTAS)   // 32
#define ROWS_PER_WARP (ROWS_PER_CTA / 8)   // 4

__device__ float g_cta_partials[NUM_CTAS];
__device__ unsigned int g_done_count = 0;

__global__ __launch_bounds__(256) void center_loss_kernel(
    const float* __restrict__ x,
    const int* __restrict__ labels,
    const float* __restrict__ centers,
    float* __restrict__ out)
{
    const int t = threadIdx.x;
    const int warp = t >> 5;
    const int lane = t & 31;
    const int cta = blockIdx.x;
    const int row_base = cta * ROWS_PER_CTA;

    __shared__ int s_lab[ROWS_PER_CTA];
    __shared__ float s_warp[8];
    __shared__ bool s_is_last;

    // Prefetch this CTA's 32 labels (one coalesced transaction).
    if (t < ROWS_PER_CTA) {
        int c = labels[row_base + t];
        s_lab[t] = min(max(c, 0), NUM_CLASSES - 1);
    }
    __syncthreads();

    const float4* __restrict__ x4 = reinterpret_cast<const float4*>(x);
    const float4* __restrict__ c4 = reinterpret_cast<const float4*>(centers);

    float acc = 0.0f;   // identical across lanes after each row's reduce

    #pragma unroll
    for (int rr = 0; rr < ROWS_PER_WARP; rr++) {
        const int local_row = warp * ROWS_PER_WARP + rr;
        const int row = row_base + local_row;
        const int cidx = s_lab[local_row];

        const float4* __restrict__ xr = x4 + (size_t)row * F4_PER_ROW;
        const float4* __restrict__ cr = c4 + (size_t)cidx * F4_PER_ROW;

        float s = 0.0f;
        #pragma unroll
        for (int i = 0; i < 4; i++) {
            float4 a = xr[i * 32 + lane];
            float4 b = cr[i * 32 + lane];
            float d0 = a.x - b.x;
            float d1 = a.y - b.y;
            float d2 = a.z - b.z;
            float d3 = a.w - b.w;
            s += d0 * d0 + d1 * d1 + d2 * d2 + d3 * d3;
        }

        // full warp reduce -> all lanes hold the row sum
        #pragma unroll
        for (int o = 16; o > 0; o >>= 1)
            s += __shfl_xor_sync(0xffffffffu, s, o);

        // per-row clamp (identity in practice: dist ~ 1000)
        s = fminf(fmaxf(s, 1e-12f), 1e12f);
        acc += s;
    }

    if (lane == 0) s_warp[warp] = acc;
    __syncthreads();

    if (t == 0) {
        float tot = 0.0f;
        #pragma unroll
        for (int w = 0; w < 8; w++) tot += s_warp[w];
        g_cta_partials[cta] = tot;
        __threadfence();
        unsigned int v = atomicAdd(&g_done_count, 1u);
        s_is_last = (v == (unsigned int)(NUM_CTAS - 1));
    }
    __syncthreads();

    if (s_is_last) {
        // 128 partials, one per thread in warps 0..3; use first 128 threads.
        float v = (t < NUM_CTAS) ? g_cta_partials[t] : 0.0f;

        #pragma unroll
        for (int o = 16; o > 0; o >>= 1)
            v += __shfl_xor_sync(0xffffffffu, v, o);

        __shared__ float fs[8];
        if (lane == 0) fs[warp] = v;
        __syncthreads();

        if (t == 0) {
            const float zero_clamp_sum =
                (float)((double)N_ROWS * (double)(NUM_CLASSES - 1) * 1e-12);
            float r = fs[0] + fs[1] + fs[2] + fs[3];  // warps 4..7 contributed 0
            out[0] = r + zero_clamp_sum + (fs[4] + fs[5] + fs[6] + fs[7]);
            g_done_count = 0;   // reset for next graph replay
        }
    }
}

extern "C" void kernel_launch(void* const* d_in, const int* in_sizes, int n_in,
                              void* d_out, int out_size)
{
    const float* x       = (const float*)d_in[0];  // (16,256,512) f32
    const int*   labels  = (const int*)d_in[1];    // (16,256) int32
    const float* centers = (const float*)d_in[2];  // (10000,512) f32
    float*       out     = (float*)d_out;          // scalar

    (void)in_sizes; (void)n_in; (void)out_size;

    center_loss_kernel<<<NUM_CTAS, 256>>>(x, labels, centers, out);
}